// round 4
// baseline (speedup 1.0000x reference)
#include <cuda_runtime.h>
#include <math.h>
#include <stdint.h>

// Problem dims
#define B_  128
#define T_  256
#define C_  384
#define H_  6
#define D_  64
#define BT  (B_*T_)      // 32768 rows
#define FF  (4*C_)       // 1536
#define QKVW (3*C_)      // 1152

// ---------------- scratch (device globals; allocation-free) ----------------
__device__ float g_h1  [BT*C_];        // LN1 out
__device__ float g_qkv [BT*QKVW];      // q|k|v per row
__device__ float g_attn[BT*C_];        // attention out (concat heads)
__device__ float g_y1  [BT*C_];        // x + attn@Wp + bp
__device__ float g_h2  [BT*C_];        // LN2 out
__device__ float g_mid [BT*FF];        // relu(h2@W1+b1)
__device__ float g_Wqkv[C_*QKVW];      // repacked QKV weights [k][n]

// ---------------- LayerNorm: one block (128 thr) per row of 384 ----------------
__global__ void ln_kernel(const float* __restrict__ x, const float* __restrict__ g,
                          const float* __restrict__ beta, float* __restrict__ out)
{
    int row = blockIdx.x;
    const float* xr = x + (size_t)row * C_;
    int tid = threadIdx.x;

    float v0 = xr[tid], v1 = xr[tid + 128], v2 = xr[tid + 256];
    float s  = v0 + v1 + v2;
    float ss = v0*v0 + v1*v1 + v2*v2;

    #pragma unroll
    for (int o = 16; o > 0; o >>= 1) {
        s  += __shfl_xor_sync(0xffffffffu, s,  o);
        ss += __shfl_xor_sync(0xffffffffu, ss, o);
    }
    __shared__ float sh[8];
    int w = tid >> 5;
    if ((tid & 31) == 0) { sh[w*2] = s; sh[w*2+1] = ss; }
    __syncthreads();
    s  = sh[0] + sh[2] + sh[4] + sh[6];
    ss = sh[1] + sh[3] + sh[5] + sh[7];

    float mean = s * (1.0f / C_);
    float var  = ss * (1.0f / C_) - mean * mean;
    float rstd = rsqrtf(var + 1e-5f);

    float* orow = out + (size_t)row * C_;
    orow[tid      ] = (v0 - mean) * rstd * g[tid      ] + beta[tid      ];
    orow[tid + 128] = (v1 - mean) * rstd * g[tid + 128] + beta[tid + 128];
    orow[tid + 256] = (v2 - mean) * rstd * g[tid + 256] + beta[tid + 256];
}

// ---------------- repack Wq/Wk/Wv (H,C,Dh) -> Wqkv[k][n], n = which*384 + h*64 + d ----
__global__ void repack_kernel(const float* __restrict__ Wq, const float* __restrict__ Wk,
                              const float* __restrict__ Wv, float* __restrict__ Wqkv)
{
    int idx = blockIdx.x * blockDim.x + threadIdx.x;
    if (idx >= C_ * QKVW) return;
    int k = idx / QKVW;
    int n = idx % QKVW;
    int which = n / C_;
    int nn = n % C_;
    int h = nn / D_, d = nn % D_;
    const float* W = (which == 0) ? Wq : (which == 1) ? Wk : Wv;
    Wqkv[idx] = W[(size_t)h * C_ * D_ + (size_t)k * D_ + d];
}

// ---------------- helpers ----------------
__device__ __forceinline__ float to_tf32(float x) {
    uint32_t y;
    asm("cvt.rna.tf32.f32 %0, %1;" : "=r"(y) : "f"(x));
    return __uint_as_float(y);
}

__device__ __forceinline__ void ldsm_x4(uint32_t* r, uint32_t addr) {
    asm volatile("ldmatrix.sync.aligned.m8n8.x4.shared.b16 {%0,%1,%2,%3}, [%4];"
                 : "=r"(r[0]), "=r"(r[1]), "=r"(r[2]), "=r"(r[3]) : "r"(addr));
}

__device__ __forceinline__ void mma_tf32(float* c, const uint32_t* a, const uint32_t* b) {
    asm volatile("mma.sync.aligned.m16n8k8.row.col.f32.tf32.tf32.f32 "
                 "{%0,%1,%2,%3}, {%4,%5,%6,%7}, {%8,%9}, {%0,%1,%2,%3};"
                 : "+f"(c[0]), "+f"(c[1]), "+f"(c[2]), "+f"(c[3])
                 : "r"(a[0]), "r"(a[1]), "r"(a[2]), "r"(a[3]), "r"(b[0]), "r"(b[1]));
}

// ---------------- tf32 tensor-core GEMM: C = A[MxK]*B[KxN] (+bias)(+res)(+relu) ------
// BM=128 BN=128 BK=32. 256 threads = 8 warps (2 along M x 4 along N), warp tile 64x32.
// A frags via ldmatrix from padded As[m][36]; B frags via scalar LDS from Bs[k][132].
// EPI: 0 = plain, 2 = +bias+residual, 3 = +bias+relu
template<int EPI>
__global__ void __launch_bounds__(256, 2)
mma_gemm(const float* __restrict__ A, const float* __restrict__ B,
         const float* __restrict__ bias, const float* __restrict__ res,
         float* __restrict__ C, int M, int N, int K)
{
    const int BM = 128, BN = 128, BK = 32;
    const int APAD = BK + 4;   // 36 floats per A row
    const int BPAD = BN + 4;   // 132 floats per B row
    __shared__ float As[BM * APAD];
    __shared__ float Bs[BK * BPAD];

    int tid  = threadIdx.x;
    int warp = tid >> 5, lane = tid & 31;
    int wm = (warp >> 2) * 64;     // warp row offset (0/64)
    int wn = (warp & 3) * 32;      // warp col offset (0/32/64/96)
    int m0 = blockIdx.y * BM, n0 = blockIdx.x * BN;

    float acc[4][4][4];
    #pragma unroll
    for (int i = 0; i < 4; i++)
        #pragma unroll
        for (int j = 0; j < 4; j++)
            #pragma unroll
            for (int r = 0; r < 4; r++) acc[i][j][r] = 0.f;

    // ldmatrix lane addressing for A (x4: blocks = [r0-7,k0-3][r8-15,k0-3][r0-7,k4-7][r8-15,k4-7])
    int a_row  = lane & 15;
    int a_kofs = (lane & 16) ? 4 : 0;
    uint32_t As_base = (uint32_t)__cvta_generic_to_shared(As);
    uint32_t addrA[4];
    #pragma unroll
    for (int mt = 0; mt < 4; mt++)
        addrA[mt] = As_base + (((wm + mt * 16 + a_row) * APAD) + a_kofs) * 4u;

    int bl = lane & 3;    // k within frag
    int bc = lane >> 2;   // n within frag

    for (int k0 = 0; k0 < K; k0 += BK) {
        // stage A tile (128x32) as float4, rounding to tf32
        #pragma unroll
        for (int i = 0; i < 4; i++) {
            int idx = tid + i * 256;
            int r = idx >> 3, cg = idx & 7;
            float4 v = *(const float4*)(A + (size_t)(m0 + r) * K + k0 + cg * 4);
            float* d = As + r * APAD + cg * 4;
            d[0] = to_tf32(v.x); d[1] = to_tf32(v.y); d[2] = to_tf32(v.z); d[3] = to_tf32(v.w);
        }
        // stage B tile (32x128) as float4, rounding to tf32 (conflict-free)
        #pragma unroll
        for (int i = 0; i < 4; i++) {
            int idx = tid + i * 256;
            int r = idx >> 5, cg = idx & 31;
            float4 v = *(const float4*)(B + (size_t)(k0 + r) * N + n0 + cg * 4);
            float* d = Bs + r * BPAD + cg * 4;
            d[0] = to_tf32(v.x); d[1] = to_tf32(v.y); d[2] = to_tf32(v.z); d[3] = to_tf32(v.w);
        }
        __syncthreads();

        #pragma unroll
        for (int ks = 0; ks < 4; ks++) {
            uint32_t afr[4][4];
            #pragma unroll
            for (int mt = 0; mt < 4; mt++)
                ldsm_x4(afr[mt], addrA[mt] + ks * 32u);   // +8 floats per k-step

            uint32_t bfr[4][2];
            #pragma unroll
            for (int nt = 0; nt < 4; nt++) {
                int nn = wn + nt * 8 + bc;
                bfr[nt][0] = __float_as_uint(Bs[(ks * 8 + bl)     * BPAD + nn]);
                bfr[nt][1] = __float_as_uint(Bs[(ks * 8 + bl + 4) * BPAD + nn]);
            }
            #pragma unroll
            for (int mt = 0; mt < 4; mt++)
                #pragma unroll
                for (int nt = 0; nt < 4; nt++)
                    mma_tf32(acc[mt][nt], afr[mt], bfr[nt]);
        }
        __syncthreads();
    }

    // epilogue
    #pragma unroll
    for (int mt = 0; mt < 4; mt++) {
        int row = m0 + wm + mt * 16 + (lane >> 2);
        #pragma unroll
        for (int nt = 0; nt < 4; nt++) {
            int col = n0 + wn + nt * 8 + 2 * (lane & 3);
            float v0 = acc[mt][nt][0], v1 = acc[mt][nt][1];
            float v2 = acc[mt][nt][2], v3 = acc[mt][nt][3];
            if (EPI >= 1) {
                float b0 = bias[col], b1 = bias[col + 1];
                v0 += b0; v1 += b1; v2 += b0; v3 += b1;
            }
            if (EPI == 2) {
                float2 r0 = *(const float2*)(res + (size_t)row * N + col);
                float2 r1 = *(const float2*)(res + (size_t)(row + 8) * N + col);
                v0 += r0.x; v1 += r0.y; v2 += r1.x; v3 += r1.y;
            }
            if (EPI == 3) {
                v0 = fmaxf(v0, 0.f); v1 = fmaxf(v1, 0.f);
                v2 = fmaxf(v2, 0.f); v3 = fmaxf(v3, 0.f);
            }
            *(float2*)(C + (size_t)row * N + col)       = make_float2(v0, v1);
            *(float2*)(C + (size_t)(row + 8) * N + col) = make_float2(v2, v3);
        }
    }
}

// ---------------- fused causal attention ----------------
// grid = B*H*2 (half query ranges), 128 threads, one query row per thread.
// K/V streamed through smem in 128-row chunks (64KB) -> 3 CTAs/SM.
__global__ void attn_kernel(const float* __restrict__ qkv, float* __restrict__ out)
{
    extern __shared__ float sm[];
    float* Ks = sm;                 // [128][64]
    float* Vs = sm + 128 * D_;      // [128][64]

    int blk  = blockIdx.x;
    int half = blk & 1;
    int bh   = blk >> 1;
    int b = bh / H_, h = bh % H_;
    int tid = threadIdx.x;          // 128
    int t = half * 128 + tid;
    const float* base = qkv + (size_t)b * T_ * QKVW;

    const float scale = 0.05103103630798287f;   // 1/sqrt(384)
    float4 q4[16];
    const float4* qr = (const float4*)(base + (size_t)t * QKVW + (size_t)h * D_);
    #pragma unroll
    for (int i = 0; i < 16; i++) {
        float4 v = qr[i];
        q4[i] = make_float4(v.x * scale, v.y * scale, v.z * scale, v.w * scale);
    }

    float m = -1e30f, l = 0.f;
    float4 o4[16];
    #pragma unroll
    for (int i = 0; i < 16; i++) o4[i] = make_float4(0.f, 0.f, 0.f, 0.f);

    for (int c = 0; c <= half; c++) {
        int s0 = c * 128;
        if (c > 0) __syncthreads();
        // cooperative chunk load: 128 rows x 64 floats = 2048 float4
        for (int idx = tid; idx < 128 * 16; idx += 128) {
            int r = idx >> 4;
            size_t roff = (size_t)(s0 + r) * QKVW + (size_t)h * D_;
            ((float4*)Ks)[idx] = *(const float4*)(base + roff + C_ + (idx & 15) * 4);
            ((float4*)Vs)[idx] = *(const float4*)(base + roff + 2 * C_ + (idx & 15) * 4);
        }
        __syncthreads();

        int send = (t < s0 + 127) ? t : (s0 + 127);
        for (int s = s0; s <= send; s++) {
            const float4* kr = (const float4*)(Ks + (s - s0) * D_);
            float x = 0.f;
            #pragma unroll
            for (int i = 0; i < 16; i++) {
                float4 k = kr[i];
                x += q4[i].x * k.x + q4[i].y * k.y + q4[i].z * k.z + q4[i].w * k.w;
            }
            float mn = fmaxf(m, x);
            float cc = __expf(m - mn);
            float p  = __expf(x - mn);
            l = l * cc + p;
            const float4* vr = (const float4*)(Vs + (s - s0) * D_);
            #pragma unroll
            for (int i = 0; i < 16; i++) {
                float4 v = vr[i];
                o4[i].x = o4[i].x * cc + p * v.x;
                o4[i].y = o4[i].y * cc + p * v.y;
                o4[i].z = o4[i].z * cc + p * v.z;
                o4[i].w = o4[i].w * cc + p * v.w;
            }
            m = mn;
        }
    }

    float inv = 1.f / l;
    float4* orow = (float4*)(out + ((size_t)(b * T_ + t)) * C_ + (size_t)h * D_);
    #pragma unroll
    for (int i = 0; i < 16; i++)
        orow[i] = make_float4(o4[i].x * inv, o4[i].y * inv, o4[i].z * inv, o4[i].w * inv);
}

// ---------------- launch ----------------
extern "C" void kernel_launch(void* const* d_in, const int* in_sizes, int n_in,
                              void* d_out, int out_size)
{
    const float* x   = (const float*)d_in[0];
    const float* Wq  = (const float*)d_in[1];
    const float* Wk  = (const float*)d_in[2];
    const float* Wv  = (const float*)d_in[3];
    const float* Wp  = (const float*)d_in[4];
    const float* bp  = (const float*)d_in[5];
    const float* W1  = (const float*)d_in[6];
    const float* b1  = (const float*)d_in[7];
    const float* W2  = (const float*)d_in[8];
    const float* b2  = (const float*)d_in[9];
    const float* g1  = (const float*)d_in[10];
    const float* be1 = (const float*)d_in[11];
    const float* g2  = (const float*)d_in[12];
    const float* be2 = (const float*)d_in[13];
    float* out = (float*)d_out;

    float *h1, *qkv, *attn, *y1, *h2, *mid, *Wqkv;
    cudaGetSymbolAddress((void**)&h1,   g_h1);
    cudaGetSymbolAddress((void**)&qkv,  g_qkv);
    cudaGetSymbolAddress((void**)&attn, g_attn);
    cudaGetSymbolAddress((void**)&y1,   g_y1);
    cudaGetSymbolAddress((void**)&h2,   g_h2);
    cudaGetSymbolAddress((void**)&mid,  g_mid);
    cudaGetSymbolAddress((void**)&Wqkv, g_Wqkv);

    static const int ATTN_SMEM = 2 * 128 * D_ * (int)sizeof(float);   // 64KB
    cudaFuncSetAttribute(attn_kernel, cudaFuncAttributeMaxDynamicSharedMemorySize, ATTN_SMEM);

    // 1. LN1
    ln_kernel<<<BT, 128>>>(x, g1, be1, h1);

    // 2. repack QKV weights
    repack_kernel<<<(C_ * QKVW + 255) / 256, 256>>>(Wq, Wk, Wv, Wqkv);

    // 3. qkv = h1 @ Wqkv           [32768 x 1152]
    mma_gemm<0><<<dim3(QKVW / 128, BT / 128), 256>>>(h1, Wqkv, nullptr, nullptr, qkv, BT, QKVW, C_);

    // 4. fused causal attention    -> attn [32768 x 384]
    attn_kernel<<<B_ * H_ * 2, 128, ATTN_SMEM>>>(qkv, attn);

    // 5. y1 = x + attn @ Wp + bp
    mma_gemm<2><<<dim3(C_ / 128, BT / 128), 256>>>(attn, Wp, bp, x, y1, BT, C_, C_);

    // 6. LN2
    ln_kernel<<<BT, 128>>>(y1, g2, be2, h2);

    // 7. mid = relu(h2 @ W1 + b1)  [32768 x 1536]
    mma_gemm<3><<<dim3(FF / 128, BT / 128), 256>>>(h2, W1, b1, nullptr, mid, BT, FF, C_);

    // 8. out = y1 + mid @ W2 + b2  [32768 x 384]
    mma_gemm<2><<<dim3(C_ / 128, BT / 128), 256>>>(mid, W2, b2, y1, out, BT, C_, FF);
}

// round 7
// speedup vs baseline: 1.4369x; 1.4369x over previous
#include <cuda_runtime.h>
#include <cuda_fp16.h>
#include <math.h>
#include <stdint.h>

// Problem dims
#define B_  128
#define T_  256
#define C_  384
#define H_  6
#define D_  64
#define BT  (B_*T_)      // 32768 rows
#define FF  (4*C_)       // 1536
#define QKVW (3*C_)      // 1152

// ---------------- scratch (device globals; allocation-free) ----------------
__device__ __half g_h1  [BT*C_];        // LN1 out (fp16)
__device__ float  g_qkv [BT*QKVW];      // q|k|v per row (fp32 for attention)
__device__ __half g_attn[BT*C_];        // attention out (fp16)
__device__ float  g_y1  [BT*C_];        // x + attn@Wp + bp
__device__ __half g_h2  [BT*C_];        // LN2 out (fp16)
__device__ __half g_mid [BT*FF];        // relu(h2@W1+b1) (fp16)
__device__ __half g_WqkvT[QKVW*C_];     // QKV weights [n][k] fp16
__device__ __half g_WpT [C_*C_];        // Wp  [n][k] fp16
__device__ __half g_W1T [FF*C_];        // W1  [n][k] fp16
__device__ __half g_W2T [C_*FF];        // W2  [n][k] fp16

// ---------------- PTX helpers ----------------
__device__ __forceinline__ void ldsm_x4(uint32_t* r, uint32_t addr) {
    asm volatile("ldmatrix.sync.aligned.m8n8.x4.shared.b16 {%0,%1,%2,%3}, [%4];"
                 : "=r"(r[0]), "=r"(r[1]), "=r"(r[2]), "=r"(r[3]) : "r"(addr));
}
__device__ __forceinline__ void ldsm_x2(uint32_t* r, uint32_t addr) {
    asm volatile("ldmatrix.sync.aligned.m8n8.x2.shared.b16 {%0,%1}, [%2];"
                 : "=r"(r[0]), "=r"(r[1]) : "r"(addr));
}
__device__ __forceinline__ void mma_f16(float* c, const uint32_t* a, const uint32_t* b) {
    asm volatile("mma.sync.aligned.m16n8k16.row.col.f32.f16.f16.f32 "
                 "{%0,%1,%2,%3}, {%4,%5,%6,%7}, {%8,%9}, {%0,%1,%2,%3};"
                 : "+f"(c[0]), "+f"(c[1]), "+f"(c[2]), "+f"(c[3])
                 : "r"(a[0]), "r"(a[1]), "r"(a[2]), "r"(a[3]), "r"(b[0]), "r"(b[1]));
}
__device__ __forceinline__ void cp16(uint32_t dst, const void* src) {
    asm volatile("cp.async.cg.shared.global [%0], [%1], 16;" :: "r"(dst), "l"(src));
}
#define CP_COMMIT() asm volatile("cp.async.commit_group;" ::: "memory")

// ---------------- LayerNorm: one block (128 thr) per row of 384, fp16 out ----------
__global__ void ln_kernel(const float* __restrict__ x, const float* __restrict__ g,
                          const float* __restrict__ beta, __half* __restrict__ out)
{
    int row = blockIdx.x;
    const float* xr = x + (size_t)row * C_;
    int tid = threadIdx.x;

    float v0 = xr[tid], v1 = xr[tid + 128], v2 = xr[tid + 256];
    float s  = v0 + v1 + v2;
    float ss = v0*v0 + v1*v1 + v2*v2;

    #pragma unroll
    for (int o = 16; o > 0; o >>= 1) {
        s  += __shfl_xor_sync(0xffffffffu, s,  o);
        ss += __shfl_xor_sync(0xffffffffu, ss, o);
    }
    __shared__ float sh[8];
    int w = tid >> 5;
    if ((tid & 31) == 0) { sh[w*2] = s; sh[w*2+1] = ss; }
    __syncthreads();
    s  = sh[0] + sh[2] + sh[4] + sh[6];
    ss = sh[1] + sh[3] + sh[5] + sh[7];

    float mean = s * (1.0f / C_);
    float var  = ss * (1.0f / C_) - mean * mean;
    float rstd = rsqrtf(var + 1e-5f);

    __half* orow = out + (size_t)row * C_;
    orow[tid      ] = __float2half_rn((v0 - mean) * rstd * g[tid      ] + beta[tid      ]);
    orow[tid + 128] = __float2half_rn((v1 - mean) * rstd * g[tid + 128] + beta[tid + 128]);
    orow[tid + 256] = __float2half_rn((v2 - mean) * rstd * g[tid + 256] + beta[tid + 256]);
}

// ------------- repack Wq/Wk/Wv (H,C,Dh) -> WqkvT[n][k] fp16, n = which*384+h*64+d ----
__global__ void repackT_kernel(const float* __restrict__ Wq, const float* __restrict__ Wk,
                               const float* __restrict__ Wv, __half* __restrict__ WqkvT)
{
    int idx = blockIdx.x * blockDim.x + threadIdx.x;
    if (idx >= QKVW * C_) return;
    int n = idx / C_;
    int k = idx % C_;
    int which = n / C_;
    int nn = n % C_;
    int h = nn / D_, d = nn % D_;
    const float* W = (which == 0) ? Wq : (which == 1) ? Wk : Wv;
    WqkvT[idx] = __float2half_rn(W[(size_t)h * C_ * D_ + (size_t)k * D_ + d]);
}

// ---------------- tiled transpose: W[K][N] fp32 -> Wt[N][K] fp16 ----------------
__global__ void transpose_kernel(const float* __restrict__ W, __half* __restrict__ Wt,
                                 int K, int N)
{
    __shared__ float tile[32][33];
    int kb = blockIdx.x * 32, nb = blockIdx.y * 32;
    int tx = threadIdx.x, ty = threadIdx.y;   // (32, 8)
    #pragma unroll
    for (int i = ty; i < 32; i += 8)
        tile[i][tx] = W[(size_t)(kb + i) * N + nb + tx];
    __syncthreads();
    #pragma unroll
    for (int i = ty; i < 32; i += 8)
        Wt[(size_t)(nb + i) * K + kb + tx] = __float2half_rn(tile[tx][i]);
}

// --------- fp16 tensor-core GEMM: C = A[MxK] * Bt[NxK]^T (+bias)(+res)(+relu) -------
// BM=128 BN=128 BK=32, 256 threads = 8 warps (2 M x 4 N), warp tile 64x32.
// A & B fragments both via ldmatrix; rows padded to 80B (conflict-free).
// cp.async double-buffered staging (2 x (10KB A + 10KB B)).
// EPI: 0 = plain, 2 = +bias+residual, 3 = +bias+relu.  OutT in {float, __half}
template<int EPI, typename OutT>
__global__ void __launch_bounds__(256)
mma_gemm(const __half* __restrict__ A, const __half* __restrict__ Bt,
         const float* __restrict__ bias, const float* __restrict__ res,
         OutT* __restrict__ C, int M, int N, int K)
{
    const int ROWB = 80;                  // bytes per padded smem row (32 fp16 + pad)
    const int TILE = 128 * ROWB;          // 10240 B
    __shared__ __align__(128) char sbuf[4 * TILE];   // [buf][A|B] = 40 KB

    uint32_t sbase = (uint32_t)__cvta_generic_to_shared(sbuf);
    int tid = threadIdx.x, warp = tid >> 5, lane = tid & 31;
    int wm = (warp >> 2) * 64;            // 0/64
    int wn = (warp & 3) * 32;             // 0/32/64/96
    int m0 = blockIdx.y * 128, n0 = blockIdx.x * 128;
    int nk = K >> 5;

    float acc[4][4][4];
    #pragma unroll
    for (int i = 0; i < 4; i++)
        #pragma unroll
        for (int j = 0; j < 4; j++)
            #pragma unroll
            for (int r = 0; r < 4; r++) acc[i][j][r] = 0.f;

    // ldmatrix lane offsets
    uint32_t arow_off[4], brow_off[4];
    #pragma unroll
    for (int mt = 0; mt < 4; mt++)
        arow_off[mt] = (uint32_t)((wm + mt * 16 + (lane & 15)) * ROWB + ((lane & 16) ? 16 : 0));
    #pragma unroll
    for (int nt = 0; nt < 4; nt++)
        brow_off[nt] = (uint32_t)((wn + nt * 8 + (lane & 7)) * ROWB + ((lane & 8) ? 16 : 0));

    // stage tile t into buffer buf via cp.async (A: 128x32 fp16, B: 128x32 fp16)
    auto stage = [&](int t, int buf) {
        int k0 = t << 5;
        uint32_t a_dst = sbase + (uint32_t)buf * 2u * TILE;
        uint32_t b_dst = a_dst + TILE;
        #pragma unroll
        for (int i = 0; i < 2; i++) {
            int idx = tid + i * 256;              // 512 chunks of 16B for A
            int r = idx >> 2, cg = idx & 3;
            cp16(a_dst + (uint32_t)(r * ROWB + cg * 16),
                 A + (size_t)(m0 + r) * K + k0 + cg * 8);
        }
        #pragma unroll
        for (int i = 0; i < 2; i++) {
            int idx = tid + i * 256;
            int r = idx >> 2, cg = idx & 3;
            cp16(b_dst + (uint32_t)(r * ROWB + cg * 16),
                 Bt + (size_t)(n0 + r) * K + k0 + cg * 8);
        }
    };

    auto compute = [&](int buf) {
        uint32_t a_base = sbase + (uint32_t)buf * 2u * TILE;
        uint32_t b_base = a_base + TILE;
        #pragma unroll
        for (int ks = 0; ks < 2; ks++) {          // two k16 steps per BK=32
            uint32_t afr[4][4];
            #pragma unroll
            for (int mt = 0; mt < 4; mt++)
                ldsm_x4(afr[mt], a_base + arow_off[mt] + ks * 32u);
            uint32_t bfr[4][2];
            #pragma unroll
            for (int nt = 0; nt < 4; nt++)
                ldsm_x2(bfr[nt], b_base + brow_off[nt] + ks * 32u);
            #pragma unroll
            for (int mt = 0; mt < 4; mt++)
                #pragma unroll
                for (int nt = 0; nt < 4; nt++)
                    mma_f16(acc[mt][nt], afr[mt], bfr[nt]);
        }
    };

    stage(0, 0);
    CP_COMMIT();
    for (int t = 0; t < nk; t++) {
        if (t + 1 < nk) {
            stage(t + 1, (t + 1) & 1);
            CP_COMMIT();
            asm volatile("cp.async.wait_group 1;" ::: "memory");
        } else {
            asm volatile("cp.async.wait_group 0;" ::: "memory");
        }
        __syncthreads();
        compute(t & 1);
        __syncthreads();
    }

    // epilogue (same fragment mapping as validated round-4 kernel)
    #pragma unroll
    for (int mt = 0; mt < 4; mt++) {
        int row = m0 + wm + mt * 16 + (lane >> 2);
        #pragma unroll
        for (int nt = 0; nt < 4; nt++) {
            int col = n0 + wn + nt * 8 + 2 * (lane & 3);
            float v0 = acc[mt][nt][0], v1 = acc[mt][nt][1];
            float v2 = acc[mt][nt][2], v3 = acc[mt][nt][3];
            if (EPI >= 1) {
                float b0 = bias[col], b1 = bias[col + 1];
                v0 += b0; v1 += b1; v2 += b0; v3 += b1;
            }
            if (EPI == 2) {
                float2 r0 = *(const float2*)(res + (size_t)row * N + col);
                float2 r1 = *(const float2*)(res + (size_t)(row + 8) * N + col);
                v0 += r0.x; v1 += r0.y; v2 += r1.x; v3 += r1.y;
            }
            if (EPI == 3) {
                v0 = fmaxf(v0, 0.f); v1 = fmaxf(v1, 0.f);
                v2 = fmaxf(v2, 0.f); v3 = fmaxf(v3, 0.f);
            }
            if (sizeof(OutT) == 4) {
                *(float2*)((float*)C + (size_t)row * N + col)       = make_float2(v0, v1);
                *(float2*)((float*)C + (size_t)(row + 8) * N + col) = make_float2(v2, v3);
            } else {
                *(__half2*)((__half*)C + (size_t)row * N + col)       = __floats2half2_rn(v0, v1);
                *(__half2*)((__half*)C + (size_t)(row + 8) * N + col) = __floats2half2_rn(v2, v3);
            }
        }
    }
}

// ---------------- fused causal attention ----------------
// grid = B*H*2 (half query ranges), 128 threads, one query row per thread.
// reads fp32 qkv, writes fp16 attn.
__global__ void attn_kernel(const float* __restrict__ qkv, __half* __restrict__ out)
{
    extern __shared__ float sm[];
    float* Ks = sm;                 // [128][64]
    float* Vs = sm + 128 * D_;      // [128][64]

    int blk  = blockIdx.x;
    int half = blk & 1;
    int bh   = blk >> 1;
    int b = bh / H_, h = bh % H_;
    int tid = threadIdx.x;          // 128
    int t = half * 128 + tid;
    const float* base = qkv + (size_t)b * T_ * QKVW;

    const float scale = 0.05103103630798287f;   // 1/sqrt(384)
    float4 q4[16];
    const float4* qr = (const float4*)(base + (size_t)t * QKVW + (size_t)h * D_);
    #pragma unroll
    for (int i = 0; i < 16; i++) {
        float4 v = qr[i];
        q4[i] = make_float4(v.x * scale, v.y * scale, v.z * scale, v.w * scale);
    }

    float m = -1e30f, l = 0.f;
    float4 o4[16];
    #pragma unroll
    for (int i = 0; i < 16; i++) o4[i] = make_float4(0.f, 0.f, 0.f, 0.f);

    for (int c = 0; c <= half; c++) {
        int s0 = c * 128;
        if (c > 0) __syncthreads();
        for (int idx = tid; idx < 128 * 16; idx += 128) {
            int r = idx >> 4;
            size_t roff = (size_t)(s0 + r) * QKVW + (size_t)h * D_;
            ((float4*)Ks)[idx] = *(const float4*)(base + roff + C_ + (idx & 15) * 4);
            ((float4*)Vs)[idx] = *(const float4*)(base + roff + 2 * C_ + (idx & 15) * 4);
        }
        __syncthreads();

        int send = (t < s0 + 127) ? t : (s0 + 127);
        for (int s = s0; s <= send; s++) {
            const float4* kr = (const float4*)(Ks + (s - s0) * D_);
            float x = 0.f;
            #pragma unroll
            for (int i = 0; i < 16; i++) {
                float4 k = kr[i];
                x += q4[i].x * k.x + q4[i].y * k.y + q4[i].z * k.z + q4[i].w * k.w;
            }
            float mn = fmaxf(m, x);
            float cc = __expf(m - mn);
            float p  = __expf(x - mn);
            l = l * cc + p;
            const float4* vr = (const float4*)(Vs + (s - s0) * D_);
            #pragma unroll
            for (int i = 0; i < 16; i++) {
                float4 v = vr[i];
                o4[i].x = o4[i].x * cc + p * v.x;
                o4[i].y = o4[i].y * cc + p * v.y;
                o4[i].z = o4[i].z * cc + p * v.z;
                o4[i].w = o4[i].w * cc + p * v.w;
            }
            m = mn;
        }
    }

    float inv = 1.f / l;
    __half2* orow = (__half2*)(out + ((size_t)(b * T_ + t)) * C_ + (size_t)h * D_);
    #pragma unroll
    for (int i = 0; i < 16; i++) {
        orow[2*i]   = __floats2half2_rn(o4[i].x * inv, o4[i].y * inv);
        orow[2*i+1] = __floats2half2_rn(o4[i].z * inv, o4[i].w * inv);
    }
}

// ---------------- launch ----------------
extern "C" void kernel_launch(void* const* d_in, const int* in_sizes, int n_in,
                              void* d_out, int out_size)
{
    const float* x   = (const float*)d_in[0];
    const float* Wq  = (const float*)d_in[1];
    const float* Wk  = (const float*)d_in[2];
    const float* Wv  = (const float*)d_in[3];
    const float* Wp  = (const float*)d_in[4];
    const float* bp  = (const float*)d_in[5];
    const float* W1  = (const float*)d_in[6];
    const float* b1  = (const float*)d_in[7];
    const float* W2  = (const float*)d_in[8];
    const float* b2  = (const float*)d_in[9];
    const float* g1  = (const float*)d_in[10];
    const float* be1 = (const float*)d_in[11];
    const float* g2  = (const float*)d_in[12];
    const float* be2 = (const float*)d_in[13];
    float* out = (float*)d_out;

    __half *h1, *attn, *h2, *mid, *WqkvT, *WpT, *W1T, *W2T;
    float *qkv, *y1;
    cudaGetSymbolAddress((void**)&h1,    g_h1);
    cudaGetSymbolAddress((void**)&qkv,   g_qkv);
    cudaGetSymbolAddress((void**)&attn,  g_attn);
    cudaGetSymbolAddress((void**)&y1,    g_y1);
    cudaGetSymbolAddress((void**)&h2,    g_h2);
    cudaGetSymbolAddress((void**)&mid,   g_mid);
    cudaGetSymbolAddress((void**)&WqkvT, g_WqkvT);
    cudaGetSymbolAddress((void**)&WpT,   g_WpT);
    cudaGetSymbolAddress((void**)&W1T,   g_W1T);
    cudaGetSymbolAddress((void**)&W2T,   g_W2T);

    static const int ATTN_SMEM = 2 * 128 * D_ * (int)sizeof(float);   // 64KB
    cudaFuncSetAttribute(attn_kernel, cudaFuncAttributeMaxDynamicSharedMemorySize, ATTN_SMEM);

    // 1. LN1 (fp16 out)
    ln_kernel<<<BT, 128>>>(x, g1, be1, h1);

    // 2. weight repack/transpose to fp16 [N][K]
    repackT_kernel<<<(QKVW * C_ + 255) / 256, 256>>>(Wq, Wk, Wv, WqkvT);
    transpose_kernel<<<dim3(C_ / 32, C_ / 32), dim3(32, 8)>>>(Wp, WpT, C_, C_);
    transpose_kernel<<<dim3(C_ / 32, FF / 32), dim3(32, 8)>>>(W1, W1T, C_, FF);
    transpose_kernel<<<dim3(FF / 32, C_ / 32), dim3(32, 8)>>>(W2, W2T, FF, C_);

    // 3. qkv = h1 @ Wqkv           [32768 x 1152] fp32 out
    mma_gemm<0, float><<<dim3(QKVW / 128, BT / 128), 256>>>(h1, WqkvT, nullptr, nullptr, qkv, BT, QKVW, C_);

    // 4. fused causal attention    -> attn [32768 x 384] fp16
    attn_kernel<<<B_ * H_ * 2, 128, ATTN_SMEM>>>(qkv, attn);

    // 5. y1 = x + attn @ Wp + bp   fp32
    mma_gemm<2, float><<<dim3(C_ / 128, BT / 128), 256>>>(attn, WpT, bp, x, y1, BT, C_, C_);

    // 6. LN2 (fp16 out)
    ln_kernel<<<BT, 128>>>(y1, g2, be2, h2);

    // 7. mid = relu(h2 @ W1 + b1)  [32768 x 1536] fp16
    mma_gemm<3, __half><<<dim3(FF / 128, BT / 128), 256>>>(h2, W1T, b1, nullptr, mid, BT, FF, C_);

    // 8. out = y1 + mid @ W2 + b2  fp32
    mma_gemm<2, float><<<dim3(C_ / 128, BT / 128), 256>>>(mid, W2T, b2, y1, out, BT, C_, FF);
}

// round 10
// speedup vs baseline: 2.0644x; 1.4367x over previous
#include <cuda_runtime.h>
#include <cuda_fp16.h>
#include <math.h>
#include <stdint.h>

// Problem dims
#define B_  128
#define T_  256
#define C_  384
#define H_  6
#define D_  64
#define BT  (B_*T_)      // 32768 rows
#define FF  (4*C_)       // 1536
#define QKVW (3*C_)      // 1152

// ---------------- scratch (device globals; allocation-free) ----------------
__device__ __half g_h1  [BT*C_];        // LN1 out (fp16)
__device__ __half g_qkv [BT*QKVW];      // q|k|v per row (fp16)
__device__ __half g_attn[BT*C_];        // attention out (fp16)
__device__ float  g_y1  [BT*C_];        // x + attn@Wp + bp
__device__ __half g_h2  [BT*C_];        // LN2 out (fp16)
__device__ __half g_mid [BT*FF];        // relu(h2@W1+b1) (fp16)
__device__ __half g_WqkvT[QKVW*C_];     // QKV weights [n][k] fp16
__device__ __half g_WpT [C_*C_];        // Wp  [n][k] fp16
__device__ __half g_W1T [FF*C_];        // W1  [n][k] fp16
__device__ __half g_W2T [C_*FF];        // W2  [n][k] fp16

// ---------------- PTX helpers ----------------
__device__ __forceinline__ void ldsm_x4(uint32_t* r, uint32_t addr) {
    asm volatile("ldmatrix.sync.aligned.m8n8.x4.shared.b16 {%0,%1,%2,%3}, [%4];"
                 : "=r"(r[0]), "=r"(r[1]), "=r"(r[2]), "=r"(r[3]) : "r"(addr));
}
__device__ __forceinline__ void ldsm_x4t(uint32_t* r, uint32_t addr) {
    asm volatile("ldmatrix.sync.aligned.m8n8.x4.trans.shared.b16 {%0,%1,%2,%3}, [%4];"
                 : "=r"(r[0]), "=r"(r[1]), "=r"(r[2]), "=r"(r[3]) : "r"(addr));
}
__device__ __forceinline__ void ldsm_x2(uint32_t* r, uint32_t addr) {
    asm volatile("ldmatrix.sync.aligned.m8n8.x2.shared.b16 {%0,%1}, [%2];"
                 : "=r"(r[0]), "=r"(r[1]) : "r"(addr));
}
__device__ __forceinline__ void mma_f16(float* c, const uint32_t* a, const uint32_t* b) {
    asm volatile("mma.sync.aligned.m16n8k16.row.col.f32.f16.f16.f32 "
                 "{%0,%1,%2,%3}, {%4,%5,%6,%7}, {%8,%9}, {%0,%1,%2,%3};"
                 : "+f"(c[0]), "+f"(c[1]), "+f"(c[2]), "+f"(c[3])
                 : "r"(a[0]), "r"(a[1]), "r"(a[2]), "r"(a[3]), "r"(b[0]), "r"(b[1]));
}
__device__ __forceinline__ uint32_t pack_h2(float lo, float hi) {
    uint32_t r;
    asm("cvt.rn.f16x2.f32 %0, %1, %2;" : "=r"(r) : "f"(hi), "f"(lo));
    return r;
}
__device__ __forceinline__ void cp16(uint32_t dst, const void* src) {
    asm volatile("cp.async.cg.shared.global [%0], [%1], 16;" :: "r"(dst), "l"(src));
}
#define CP_COMMIT() asm volatile("cp.async.commit_group;" ::: "memory")

// ---------------- LayerNorm: one block (128 thr) per row of 384, fp16 out ----------
__global__ void ln_kernel(const float* __restrict__ x, const float* __restrict__ g,
                          const float* __restrict__ beta, __half* __restrict__ out)
{
    int row = blockIdx.x;
    const float* xr = x + (size_t)row * C_;
    int tid = threadIdx.x;

    float v0 = xr[tid], v1 = xr[tid + 128], v2 = xr[tid + 256];
    float s  = v0 + v1 + v2;
    float ss = v0*v0 + v1*v1 + v2*v2;

    #pragma unroll
    for (int o = 16; o > 0; o >>= 1) {
        s  += __shfl_xor_sync(0xffffffffu, s,  o);
        ss += __shfl_xor_sync(0xffffffffu, ss, o);
    }
    __shared__ float sh[8];
    int w = tid >> 5;
    if ((tid & 31) == 0) { sh[w*2] = s; sh[w*2+1] = ss; }
    __syncthreads();
    s  = sh[0] + sh[2] + sh[4] + sh[6];
    ss = sh[1] + sh[3] + sh[5] + sh[7];

    float mean = s * (1.0f / C_);
    float var  = ss * (1.0f / C_) - mean * mean;
    float rstd = rsqrtf(var + 1e-5f);

    __half* orow = out + (size_t)row * C_;
    orow[tid      ] = __float2half_rn((v0 - mean) * rstd * g[tid      ] + beta[tid      ]);
    orow[tid + 128] = __float2half_rn((v1 - mean) * rstd * g[tid + 128] + beta[tid + 128]);
    orow[tid + 256] = __float2half_rn((v2 - mean) * rstd * g[tid + 256] + beta[tid + 256]);
}

// ------------- repack Wq/Wk/Wv (H,C,Dh) -> WqkvT[n][k] fp16, n = which*384+h*64+d ----
__global__ void repackT_kernel(const float* __restrict__ Wq, const float* __restrict__ Wk,
                               const float* __restrict__ Wv, __half* __restrict__ WqkvT)
{
    int idx = blockIdx.x * blockDim.x + threadIdx.x;
    if (idx >= QKVW * C_) return;
    int n = idx / C_;
    int k = idx % C_;
    int which = n / C_;
    int nn = n % C_;
    int h = nn / D_, d = nn % D_;
    const float* W = (which == 0) ? Wq : (which == 1) ? Wk : Wv;
    WqkvT[idx] = __float2half_rn(W[(size_t)h * C_ * D_ + (size_t)k * D_ + d]);
}

// ---------------- tiled transpose: W[K][N] fp32 -> Wt[N][K] fp16 ----------------
__global__ void transpose_kernel(const float* __restrict__ W, __half* __restrict__ Wt,
                                 int K, int N)
{
    __shared__ float tile[32][33];
    int kb = blockIdx.x * 32, nb = blockIdx.y * 32;
    int tx = threadIdx.x, ty = threadIdx.y;   // (32, 8)
    #pragma unroll
    for (int i = ty; i < 32; i += 8)
        tile[i][tx] = W[(size_t)(kb + i) * N + nb + tx];
    __syncthreads();
    #pragma unroll
    for (int i = ty; i < 32; i += 8)
        Wt[(size_t)(nb + i) * K + kb + tx] = __float2half_rn(tile[tx][i]);
}

// --------- fp16 tensor-core GEMM: C = A[MxK] * Bt[NxK]^T (+bias)(+res)(+relu) -------
template<int EPI, typename OutT>
__global__ void __launch_bounds__(256)
mma_gemm(const __half* __restrict__ A, const __half* __restrict__ Bt,
         const float* __restrict__ bias, const float* __restrict__ res,
         OutT* __restrict__ C, int M, int N, int K)
{
    const int ROWB = 80;
    const int TILE = 128 * ROWB;
    __shared__ __align__(128) char sbuf[4 * TILE];

    uint32_t sbase = (uint32_t)__cvta_generic_to_shared(sbuf);
    int tid = threadIdx.x, warp = tid >> 5, lane = tid & 31;
    int wm = (warp >> 2) * 64;
    int wn = (warp & 3) * 32;
    int m0 = blockIdx.y * 128, n0 = blockIdx.x * 128;
    int nk = K >> 5;

    float acc[4][4][4];
    #pragma unroll
    for (int i = 0; i < 4; i++)
        #pragma unroll
        for (int j = 0; j < 4; j++)
            #pragma unroll
            for (int r = 0; r < 4; r++) acc[i][j][r] = 0.f;

    uint32_t arow_off[4], brow_off[4];
    #pragma unroll
    for (int mt = 0; mt < 4; mt++)
        arow_off[mt] = (uint32_t)((wm + mt * 16 + (lane & 15)) * ROWB + ((lane & 16) ? 16 : 0));
    #pragma unroll
    for (int nt = 0; nt < 4; nt++)
        brow_off[nt] = (uint32_t)((wn + nt * 8 + (lane & 7)) * ROWB + ((lane & 8) ? 16 : 0));

    auto stage = [&](int t, int buf) {
        int k0 = t << 5;
        uint32_t a_dst = sbase + (uint32_t)buf * 2u * TILE;
        uint32_t b_dst = a_dst + TILE;
        #pragma unroll
        for (int i = 0; i < 2; i++) {
            int idx = tid + i * 256;
            int r = idx >> 2, cg = idx & 3;
            cp16(a_dst + (uint32_t)(r * ROWB + cg * 16),
                 A + (size_t)(m0 + r) * K + k0 + cg * 8);
        }
        #pragma unroll
        for (int i = 0; i < 2; i++) {
            int idx = tid + i * 256;
            int r = idx >> 2, cg = idx & 3;
            cp16(b_dst + (uint32_t)(r * ROWB + cg * 16),
                 Bt + (size_t)(n0 + r) * K + k0 + cg * 8);
        }
    };

    auto compute = [&](int buf) {
        uint32_t a_base = sbase + (uint32_t)buf * 2u * TILE;
        uint32_t b_base = a_base + TILE;
        #pragma unroll
        for (int ks = 0; ks < 2; ks++) {
            uint32_t afr[4][4];
            #pragma unroll
            for (int mt = 0; mt < 4; mt++)
                ldsm_x4(afr[mt], a_base + arow_off[mt] + ks * 32u);
            uint32_t bfr[4][2];
            #pragma unroll
            for (int nt = 0; nt < 4; nt++)
                ldsm_x2(bfr[nt], b_base + brow_off[nt] + ks * 32u);
            #pragma unroll
            for (int mt = 0; mt < 4; mt++)
                #pragma unroll
                for (int nt = 0; nt < 4; nt++)
                    mma_f16(acc[mt][nt], afr[mt], bfr[nt]);
        }
    };

    stage(0, 0);
    CP_COMMIT();
    for (int t = 0; t < nk; t++) {
        if (t + 1 < nk) {
            stage(t + 1, (t + 1) & 1);
            CP_COMMIT();
            asm volatile("cp.async.wait_group 1;" ::: "memory");
        } else {
            asm volatile("cp.async.wait_group 0;" ::: "memory");
        }
        __syncthreads();
        compute(t & 1);
        __syncthreads();
    }

    #pragma unroll
    for (int mt = 0; mt < 4; mt++) {
        int row = m0 + wm + mt * 16 + (lane >> 2);
        #pragma unroll
        for (int nt = 0; nt < 4; nt++) {
            int col = n0 + wn + nt * 8 + 2 * (lane & 3);
            float v0 = acc[mt][nt][0], v1 = acc[mt][nt][1];
            float v2 = acc[mt][nt][2], v3 = acc[mt][nt][3];
            if (EPI >= 1) {
                float b0 = bias[col], b1 = bias[col + 1];
                v0 += b0; v1 += b1; v2 += b0; v3 += b1;
            }
            if (EPI == 2) {
                float2 r0 = *(const float2*)(res + (size_t)row * N + col);
                float2 r1 = *(const float2*)(res + (size_t)(row + 8) * N + col);
                v0 += r0.x; v1 += r0.y; v2 += r1.x; v3 += r1.y;
            }
            if (EPI == 3) {
                v0 = fmaxf(v0, 0.f); v1 = fmaxf(v1, 0.f);
                v2 = fmaxf(v2, 0.f); v3 = fmaxf(v3, 0.f);
            }
            if (sizeof(OutT) == 4) {
                *(float2*)((float*)C + (size_t)row * N + col)       = make_float2(v0, v1);
                *(float2*)((float*)C + (size_t)(row + 8) * N + col) = make_float2(v2, v3);
            } else {
                *(__half2*)((__half*)C + (size_t)row * N + col)       = __floats2half2_rn(v0, v1);
                *(__half2*)((__half*)C + (size_t)(row + 8) * N + col) = __floats2half2_rn(v2, v3);
            }
        }
    }
}

// ---------------- MMA flash attention (causal) ----------------
// grid = (2 q-tiles, B*H). 256 threads = 8 warps x 16 query rows.
// S = Q@K^T via mma fp16, online softmax in fp32 regs, P reused as A-frags for P@V.
#define ASTR 72   // smem row stride in halves (144B: conflict-free ldmatrix)
__global__ void __launch_bounds__(256)
fattn_kernel(const __half* __restrict__ qkv, __half* __restrict__ out)
{
    extern __shared__ __half sm[];
    __half* Qs = sm;                  // [128][ASTR]
    __half* Ks = sm + 128 * ASTR;
    __half* Vs = Ks + 128 * ASTR;

    int qt = blockIdx.x;              // 0/1
    int bh = blockIdx.y;
    int b = bh / H_, h = bh % H_;
    int tid = threadIdx.x, warp = tid >> 5, lane = tid & 31;
    int wm = warp * 16;
    int q0 = qt * 128;
    const __half* base = qkv + (size_t)b * T_ * QKVW + (size_t)h * D_;

    uint32_t qs_a = (uint32_t)__cvta_generic_to_shared(Qs);
    uint32_t ks_a = (uint32_t)__cvta_generic_to_shared(Ks);
    uint32_t vs_a = (uint32_t)__cvta_generic_to_shared(Vs);

    // load Q tile (128 x 64 halves)
    for (int i = tid; i < 128 * 8; i += 256) {
        int r = i >> 3, c = i & 7;
        *(float4*)(Qs + r * ASTR + c * 8) =
            *(const float4*)(base + (size_t)(q0 + r) * QKVW + c * 8);
    }

    // softmax state + O accum
    float mlo = -1e30f, mhi = -1e30f, llo = 0.f, lhi = 0.f;
    float oacc[8][4];
    #pragma unroll
    for (int j = 0; j < 8; j++)
        #pragma unroll
        for (int e = 0; e < 4; e++) oacc[j][e] = 0.f;

    const float scale = 0.05103103630798287f;   // 1/sqrt(384)
    int qlo_g = q0 + wm + (lane >> 2);
    int qhi_g = qlo_g + 8;

    uint32_t qf[4][4];   // Q A-frags, loaded after first sync

    for (int kt = 0; kt <= qt; kt++) {
        int k0 = kt * 128;
        bool diag = (kt == qt);
        if (kt > 0) __syncthreads();
        // load K,V tiles
        for (int i = tid; i < 128 * 8; i += 256) {
            int r = i >> 3, c = i & 7;
            size_t roff = (size_t)(k0 + r) * QKVW + c * 8;
            *(float4*)(Ks + r * ASTR + c * 8) = *(const float4*)(base + C_  + roff);
            *(float4*)(Vs + r * ASTR + c * 8) = *(const float4*)(base + 2*C_ + roff);
        }
        __syncthreads();

        if (kt == 0) {
            #pragma unroll
            for (int kk = 0; kk < 4; kk++)
                ldsm_x4(qf[kk], qs_a + (uint32_t)(((wm + (lane & 15)) * ASTR
                                     + kk * 16 + ((lane >> 4) & 1) * 8) * 2));
        }

        // ---- S = Q @ K^T : sacc[16 n-tiles][4] ----
        float sacc[16][4];
        #pragma unroll
        for (int j = 0; j < 16; j++)
            #pragma unroll
            for (int e = 0; e < 4; e++) sacc[j][e] = 0.f;

        #pragma unroll
        for (int kk = 0; kk < 4; kk++) {
            #pragma unroll
            for (int j2 = 0; j2 < 8; j2++) {
                uint32_t kb[4];
                ldsm_x4(kb, ks_a + (uint32_t)(((j2 * 16 + ((lane >> 4) & 1) * 8 + (lane & 7)) * ASTR
                                   + kk * 16 + ((lane >> 3) & 1) * 8) * 2));
                mma_f16(sacc[2*j2],     qf[kk], kb);
                mma_f16(sacc[2*j2 + 1], qf[kk], kb + 2);
            }
        }

        // ---- scale + causal mask + row max ----
        float rmlo = -1e30f, rmhi = -1e30f;
        #pragma unroll
        for (int j = 0; j < 16; j++) {
            int key = k0 + 8 * j + 2 * (lane & 3);
            #pragma unroll
            for (int e = 0; e < 2; e++) {
                float s = sacc[j][e] * scale;
                if (diag && (key + e > qlo_g)) s = -1e30f;
                sacc[j][e] = s;
                rmlo = fmaxf(rmlo, s);
            }
            #pragma unroll
            for (int e = 2; e < 4; e++) {
                float s = sacc[j][e] * scale;
                if (diag && (key + e - 2 > qhi_g)) s = -1e30f;
                sacc[j][e] = s;
                rmhi = fmaxf(rmhi, s);
            }
        }
        rmlo = fmaxf(rmlo, __shfl_xor_sync(0xffffffffu, rmlo, 1));
        rmlo = fmaxf(rmlo, __shfl_xor_sync(0xffffffffu, rmlo, 2));
        rmhi = fmaxf(rmhi, __shfl_xor_sync(0xffffffffu, rmhi, 1));
        rmhi = fmaxf(rmhi, __shfl_xor_sync(0xffffffffu, rmhi, 2));

        float mnlo = fmaxf(mlo, rmlo), mnhi = fmaxf(mhi, rmhi);
        float elo = __expf(mlo - mnlo), ehi = __expf(mhi - mnhi);
        mlo = mnlo; mhi = mnhi;

        // ---- p = exp(s - m), row sums ----
        float slo = 0.f, shi = 0.f;
        #pragma unroll
        for (int j = 0; j < 16; j++) {
            float p0 = __expf(sacc[j][0] - mnlo);
            float p1 = __expf(sacc[j][1] - mnlo);
            float p2 = __expf(sacc[j][2] - mnhi);
            float p3 = __expf(sacc[j][3] - mnhi);
            sacc[j][0] = p0; sacc[j][1] = p1; sacc[j][2] = p2; sacc[j][3] = p3;
            slo += p0 + p1; shi += p2 + p3;
        }
        slo += __shfl_xor_sync(0xffffffffu, slo, 1);
        slo += __shfl_xor_sync(0xffffffffu, slo, 2);
        shi += __shfl_xor_sync(0xffffffffu, shi, 1);
        shi += __shfl_xor_sync(0xffffffffu, shi, 2);
        llo = llo * elo + slo;
        lhi = lhi * ehi + shi;

        // rescale O
        #pragma unroll
        for (int j = 0; j < 8; j++) {
            oacc[j][0] *= elo; oacc[j][1] *= elo;
            oacc[j][2] *= ehi; oacc[j][3] *= ehi;
        }

        // ---- O += P @ V ----
        #pragma unroll
        for (int kk2 = 0; kk2 < 8; kk2++) {
            uint32_t pa[4];
            pa[0] = pack_h2(sacc[2*kk2][0],   sacc[2*kk2][1]);
            pa[1] = pack_h2(sacc[2*kk2][2],   sacc[2*kk2][3]);
            pa[2] = pack_h2(sacc[2*kk2+1][0], sacc[2*kk2+1][1]);
            pa[3] = pack_h2(sacc[2*kk2+1][2], sacc[2*kk2+1][3]);
            #pragma unroll
            for (int j2 = 0; j2 < 4; j2++) {
                uint32_t vb[4];
                ldsm_x4t(vb, vs_a + (uint32_t)(((kk2 * 16 + ((lane >> 3) & 1) * 8 + (lane & 7)) * ASTR
                                    + j2 * 16 + ((lane >> 4) & 1) * 8) * 2));
                mma_f16(oacc[2*j2],     pa, vb);
                mma_f16(oacc[2*j2 + 1], pa, vb + 2);
            }
        }
    }

    // ---- write O / l ----
    float ilo = 1.f / llo, ihi = 1.f / lhi;
    size_t rlo = (size_t)(b * T_ + qlo_g) * C_ + (size_t)h * D_;
    size_t rhi = (size_t)(b * T_ + qhi_g) * C_ + (size_t)h * D_;
    #pragma unroll
    for (int j = 0; j < 8; j++) {
        int col = 8 * j + 2 * (lane & 3);
        *(__half2*)(out + rlo + col) = __floats2half2_rn(oacc[j][0] * ilo, oacc[j][1] * ilo);
        *(__half2*)(out + rhi + col) = __floats2half2_rn(oacc[j][2] * ihi, oacc[j][3] * ihi);
    }
}

// ---------------- launch ----------------
extern "C" void kernel_launch(void* const* d_in, const int* in_sizes, int n_in,
                              void* d_out, int out_size)
{
    const float* x   = (const float*)d_in[0];
    const float* Wq  = (const float*)d_in[1];
    const float* Wk  = (const float*)d_in[2];
    const float* Wv  = (const float*)d_in[3];
    const float* Wp  = (const float*)d_in[4];
    const float* bp  = (const float*)d_in[5];
    const float* W1  = (const float*)d_in[6];
    const float* b1  = (const float*)d_in[7];
    const float* W2  = (const float*)d_in[8];
    const float* b2  = (const float*)d_in[9];
    const float* g1  = (const float*)d_in[10];
    const float* be1 = (const float*)d_in[11];
    const float* g2  = (const float*)d_in[12];
    const float* be2 = (const float*)d_in[13];
    float* out = (float*)d_out;

    __half *h1, *qkv, *attn, *h2, *mid, *WqkvT, *WpT, *W1T, *W2T;
    float *y1;
    cudaGetSymbolAddress((void**)&h1,    g_h1);
    cudaGetSymbolAddress((void**)&qkv,   g_qkv);
    cudaGetSymbolAddress((void**)&attn,  g_attn);
    cudaGetSymbolAddress((void**)&y1,    g_y1);
    cudaGetSymbolAddress((void**)&h2,    g_h2);
    cudaGetSymbolAddress((void**)&mid,   g_mid);
    cudaGetSymbolAddress((void**)&WqkvT, g_WqkvT);
    cudaGetSymbolAddress((void**)&WpT,   g_WpT);
    cudaGetSymbolAddress((void**)&W1T,   g_W1T);
    cudaGetSymbolAddress((void**)&W2T,   g_W2T);

    static const int FATTN_SMEM = 3 * 128 * ASTR * (int)sizeof(__half);   // 55296
    cudaFuncSetAttribute(fattn_kernel, cudaFuncAttributeMaxDynamicSharedMemorySize, FATTN_SMEM);

    // 1. LN1 (fp16 out)
    ln_kernel<<<BT, 128>>>(x, g1, be1, h1);

    // 2. weight repack/transpose to fp16 [N][K]
    repackT_kernel<<<(QKVW * C_ + 255) / 256, 256>>>(Wq, Wk, Wv, WqkvT);
    transpose_kernel<<<dim3(C_ / 32, C_ / 32), dim3(32, 8)>>>(Wp, WpT, C_, C_);
    transpose_kernel<<<dim3(C_ / 32, FF / 32), dim3(32, 8)>>>(W1, W1T, C_, FF);
    transpose_kernel<<<dim3(FF / 32, C_ / 32), dim3(32, 8)>>>(W2, W2T, FF, C_);

    // 3. qkv = h1 @ Wqkv           [32768 x 1152] fp16
    mma_gemm<0, __half><<<dim3(QKVW / 128, BT / 128), 256>>>(h1, WqkvT, nullptr, nullptr, qkv, BT, QKVW, C_);

    // 4. MMA flash attention       -> attn [32768 x 384] fp16
    fattn_kernel<<<dim3(2, B_ * H_), 256, FATTN_SMEM>>>(qkv, attn);

    // 5. y1 = x + attn @ Wp + bp   fp32
    mma_gemm<2, float><<<dim3(C_ / 128, BT / 128), 256>>>(attn, WpT, bp, x, y1, BT, C_, C_);

    // 6. LN2 (fp16 out)
    ln_kernel<<<BT, 128>>>(y1, g2, be2, h2);

    // 7. mid = relu(h2 @ W1 + b1)  [32768 x 1536] fp16
    mma_gemm<3, __half><<<dim3(FF / 128, BT / 128), 256>>>(h2, W1T, b1, nullptr, mid, BT, FF, C_);

    // 8. out = y1 + mid @ W2 + b2  fp32
    mma_gemm<2, float><<<dim3(C_ / 128, BT / 128), 256>>>(mid, W2T, b2, y1, out, BT, C_, FF);
}

// round 11
// speedup vs baseline: 2.3203x; 1.1239x over previous
#include <cuda_runtime.h>
#include <cuda_fp16.h>
#include <math.h>
#include <stdint.h>

// Problem dims
#define B_  128
#define T_  256
#define C_  384
#define H_  6
#define D_  64
#define BT  (B_*T_)      // 32768 rows
#define FF  (4*C_)       // 1536
#define QKVW (3*C_)      // 1152

// ---------------- scratch (device globals; allocation-free) ----------------
__device__ __half g_h1  [BT*C_];        // LN1 out (fp16)
__device__ __half g_qkv [BT*QKVW];      // q|k|v per row (fp16)
__device__ __half g_attn[BT*C_];        // attention out (fp16)
__device__ float  g_y1  [BT*C_];        // x + attn@Wp + bp
__device__ __half g_h2  [BT*C_];        // LN2 out (fp16)
__device__ __half g_mid [BT*FF];        // relu(h2@W1+b1) (fp16)
__device__ __half g_WqkvT[QKVW*C_];     // QKV weights [n][k] fp16
__device__ __half g_WpT [C_*C_];        // Wp  [n][k] fp16
__device__ __half g_W1T [FF*C_];        // W1  [n][k] fp16
__device__ __half g_W2T [C_*FF];        // W2  [n][k] fp16

// ---------------- PTX helpers ----------------
__device__ __forceinline__ void ldsm_x4(uint32_t* r, uint32_t addr) {
    asm volatile("ldmatrix.sync.aligned.m8n8.x4.shared.b16 {%0,%1,%2,%3}, [%4];"
                 : "=r"(r[0]), "=r"(r[1]), "=r"(r[2]), "=r"(r[3]) : "r"(addr));
}
__device__ __forceinline__ void ldsm_x4t(uint32_t* r, uint32_t addr) {
    asm volatile("ldmatrix.sync.aligned.m8n8.x4.trans.shared.b16 {%0,%1,%2,%3}, [%4];"
                 : "=r"(r[0]), "=r"(r[1]), "=r"(r[2]), "=r"(r[3]) : "r"(addr));
}
__device__ __forceinline__ void ldsm_x2(uint32_t* r, uint32_t addr) {
    asm volatile("ldmatrix.sync.aligned.m8n8.x2.shared.b16 {%0,%1}, [%2];"
                 : "=r"(r[0]), "=r"(r[1]) : "r"(addr));
}
__device__ __forceinline__ void mma_f16(float* c, const uint32_t* a, const uint32_t* b) {
    asm volatile("mma.sync.aligned.m16n8k16.row.col.f32.f16.f16.f32 "
                 "{%0,%1,%2,%3}, {%4,%5,%6,%7}, {%8,%9}, {%0,%1,%2,%3};"
                 : "+f"(c[0]), "+f"(c[1]), "+f"(c[2]), "+f"(c[3])
                 : "r"(a[0]), "r"(a[1]), "r"(a[2]), "r"(a[3]), "r"(b[0]), "r"(b[1]));
}
__device__ __forceinline__ uint32_t pack_h2(float lo, float hi) {
    uint32_t r;
    asm("cvt.rn.f16x2.f32 %0, %1, %2;" : "=r"(r) : "f"(hi), "f"(lo));
    return r;
}
__device__ __forceinline__ void cp16(uint32_t dst, const void* src) {
    asm volatile("cp.async.cg.shared.global [%0], [%1], 16;" :: "r"(dst), "l"(src));
}
#define CP_COMMIT() asm volatile("cp.async.commit_group;" ::: "memory")

// ---------------- LayerNorm: one warp per row of 384, fp16 out ----------------
__global__ void ln_kernel(const float* __restrict__ x, const float* __restrict__ g,
                          const float* __restrict__ beta, __half* __restrict__ out)
{
    int row  = blockIdx.x * 4 + (threadIdx.x >> 5);
    int lane = threadIdx.x & 31;
    const float4* xr = (const float4*)(x + (size_t)row * C_);

    float4 v[3];
    float s = 0.f, ss = 0.f;
    #pragma unroll
    for (int i = 0; i < 3; i++) {
        v[i] = xr[lane + i * 32];
        s  += v[i].x + v[i].y + v[i].z + v[i].w;
        ss += v[i].x*v[i].x + v[i].y*v[i].y + v[i].z*v[i].z + v[i].w*v[i].w;
    }
    #pragma unroll
    for (int o = 16; o > 0; o >>= 1) {
        s  += __shfl_xor_sync(0xffffffffu, s,  o);
        ss += __shfl_xor_sync(0xffffffffu, ss, o);
    }
    float mean = s * (1.0f / C_);
    float var  = ss * (1.0f / C_) - mean * mean;
    float rstd = rsqrtf(var + 1e-5f);

    __half* orow = out + (size_t)row * C_;
    #pragma unroll
    for (int i = 0; i < 3; i++) {
        int c = (lane + i * 32) * 4;
        float4 gg = *(const float4*)(g + c);
        float4 bb = *(const float4*)(beta + c);
        float e0 = (v[i].x - mean) * rstd * gg.x + bb.x;
        float e1 = (v[i].y - mean) * rstd * gg.y + bb.y;
        float e2 = (v[i].z - mean) * rstd * gg.z + bb.z;
        float e3 = (v[i].w - mean) * rstd * gg.w + bb.w;
        *(__half2*)(orow + c)     = __floats2half2_rn(e0, e1);
        *(__half2*)(orow + c + 2) = __floats2half2_rn(e2, e3);
    }
}

// ------------- repack Wq/Wk/Wv (H,C,Dh) -> WqkvT[n][k] fp16, n = which*384+h*64+d ----
__global__ void repackT_kernel(const float* __restrict__ Wq, const float* __restrict__ Wk,
                               const float* __restrict__ Wv, __half* __restrict__ WqkvT)
{
    int idx = blockIdx.x * blockDim.x + threadIdx.x;
    if (idx >= QKVW * C_) return;
    int n = idx / C_;
    int k = idx % C_;
    int which = n / C_;
    int nn = n % C_;
    int h = nn / D_, d = nn % D_;
    const float* W = (which == 0) ? Wq : (which == 1) ? Wk : Wv;
    WqkvT[idx] = __float2half_rn(W[(size_t)h * C_ * D_ + (size_t)k * D_ + d]);
}

// ---------------- tiled transpose: W[K][N] fp32 -> Wt[N][K] fp16 ----------------
__global__ void transpose_kernel(const float* __restrict__ W, __half* __restrict__ Wt,
                                 int K, int N)
{
    __shared__ float tile[32][33];
    int kb = blockIdx.x * 32, nb = blockIdx.y * 32;
    int tx = threadIdx.x, ty = threadIdx.y;   // (32, 8)
    #pragma unroll
    for (int i = ty; i < 32; i += 8)
        tile[i][tx] = W[(size_t)(kb + i) * N + nb + tx];
    __syncthreads();
    #pragma unroll
    for (int i = ty; i < 32; i += 8)
        Wt[(size_t)(nb + i) * K + kb + tx] = __float2half_rn(tile[tx][i]);
}

// --------- fp16 tensor-core GEMM: C = A[MxK] * Bt[NxK]^T (+bias)(+res)(+relu) -------
// BM=128 BN=128 BK=32, 256 threads, 3-stage cp.async pipeline, one sync per k-iter.
template<int EPI, typename OutT>
__global__ void __launch_bounds__(256)
mma_gemm(const __half* __restrict__ A, const __half* __restrict__ Bt,
         const float* __restrict__ bias, const float* __restrict__ res,
         OutT* __restrict__ C, int M, int N, int K)
{
    const int ROWB = 80;                // bytes per padded smem row
    const int TILE = 128 * ROWB;        // 10240
    const int STG  = 2 * TILE;          // A+B per stage = 20480
    extern __shared__ __align__(128) char sbuf[];    // 3 * STG = 61440

    uint32_t sbase = (uint32_t)__cvta_generic_to_shared(sbuf);
    int tid = threadIdx.x, warp = tid >> 5, lane = tid & 31;
    int wm = (warp >> 2) * 64;
    int wn = (warp & 3) * 32;
    int m0 = blockIdx.y * 128, n0 = blockIdx.x * 128;
    int nk = K >> 5;

    float acc[4][4][4];
    #pragma unroll
    for (int i = 0; i < 4; i++)
        #pragma unroll
        for (int j = 0; j < 4; j++)
            #pragma unroll
            for (int r = 0; r < 4; r++) acc[i][j][r] = 0.f;

    uint32_t arow_off[4], brow_off[4];
    #pragma unroll
    for (int mt = 0; mt < 4; mt++)
        arow_off[mt] = (uint32_t)((wm + mt * 16 + (lane & 15)) * ROWB + ((lane & 16) ? 16 : 0));
    #pragma unroll
    for (int nt = 0; nt < 4; nt++)
        brow_off[nt] = (uint32_t)((wn + nt * 8 + (lane & 7)) * ROWB + ((lane & 8) ? 16 : 0));

    auto stage = [&](int t, int buf) {
        int k0 = t << 5;
        uint32_t a_dst = sbase + (uint32_t)buf * STG;
        uint32_t b_dst = a_dst + TILE;
        #pragma unroll
        for (int i = 0; i < 2; i++) {
            int idx = tid + i * 256;
            int r = idx >> 2, cg = idx & 3;
            cp16(a_dst + (uint32_t)(r * ROWB + cg * 16),
                 A + (size_t)(m0 + r) * K + k0 + cg * 8);
        }
        #pragma unroll
        for (int i = 0; i < 2; i++) {
            int idx = tid + i * 256;
            int r = idx >> 2, cg = idx & 3;
            cp16(b_dst + (uint32_t)(r * ROWB + cg * 16),
                 Bt + (size_t)(n0 + r) * K + k0 + cg * 8);
        }
    };

    auto compute = [&](int buf) {
        uint32_t a_base = sbase + (uint32_t)buf * STG;
        uint32_t b_base = a_base + TILE;
        #pragma unroll
        for (int ks = 0; ks < 2; ks++) {
            uint32_t afr[4][4];
            #pragma unroll
            for (int mt = 0; mt < 4; mt++)
                ldsm_x4(afr[mt], a_base + arow_off[mt] + ks * 32u);
            uint32_t bfr[4][2];
            #pragma unroll
            for (int nt = 0; nt < 4; nt++)
                ldsm_x2(bfr[nt], b_base + brow_off[nt] + ks * 32u);
            #pragma unroll
            for (int mt = 0; mt < 4; mt++)
                #pragma unroll
                for (int nt = 0; nt < 4; nt++)
                    mma_f16(acc[mt][nt], afr[mt], bfr[nt]);
        }
    };

    // prologue: 2 stages in flight
    stage(0, 0); CP_COMMIT();
    stage(1, 1); CP_COMMIT();

    int buf = 0;
    for (int t = 0; t < nk; t++) {
        if (t < nk - 1) asm volatile("cp.async.wait_group 1;" ::: "memory");
        else            asm volatile("cp.async.wait_group 0;" ::: "memory");
        __syncthreads();
        if (t + 2 < nk) {
            int nb = buf + 2; if (nb >= 3) nb -= 3;
            stage(t + 2, nb);
            CP_COMMIT();
        }
        compute(buf);
        if (++buf == 3) buf = 0;
    }

    #pragma unroll
    for (int mt = 0; mt < 4; mt++) {
        int row = m0 + wm + mt * 16 + (lane >> 2);
        #pragma unroll
        for (int nt = 0; nt < 4; nt++) {
            int col = n0 + wn + nt * 8 + 2 * (lane & 3);
            float v0 = acc[mt][nt][0], v1 = acc[mt][nt][1];
            float v2 = acc[mt][nt][2], v3 = acc[mt][nt][3];
            if (EPI >= 1) {
                float b0 = bias[col], b1 = bias[col + 1];
                v0 += b0; v1 += b1; v2 += b0; v3 += b1;
            }
            if (EPI == 2) {
                float2 r0 = *(const float2*)(res + (size_t)row * N + col);
                float2 r1 = *(const float2*)(res + (size_t)(row + 8) * N + col);
                v0 += r0.x; v1 += r0.y; v2 += r1.x; v3 += r1.y;
            }
            if (EPI == 3) {
                v0 = fmaxf(v0, 0.f); v1 = fmaxf(v1, 0.f);
                v2 = fmaxf(v2, 0.f); v3 = fmaxf(v3, 0.f);
            }
            if (sizeof(OutT) == 4) {
                *(float2*)((float*)C + (size_t)row * N + col)       = make_float2(v0, v1);
                *(float2*)((float*)C + (size_t)(row + 8) * N + col) = make_float2(v2, v3);
            } else {
                *(__half2*)((__half*)C + (size_t)row * N + col)       = __floats2half2_rn(v0, v1);
                *(__half2*)((__half*)C + (size_t)(row + 8) * N + col) = __floats2half2_rn(v2, v3);
            }
        }
    }
}

// ---------------- MMA flash attention (causal), 64-key chunks ----------------
// grid = (2 q-tiles, B*H). 256 threads = 8 warps x 16 query rows. 2 CTAs/SM.
#define ASTR 72   // smem row stride in halves (144B: conflict-free ldmatrix)
__global__ void __launch_bounds__(256, 2)
fattn_kernel(const __half* __restrict__ qkv, __half* __restrict__ out)
{
    extern __shared__ __half sm[];
    __half* Qs = sm;                  // [128][ASTR]
    __half* Ks = sm + 128 * ASTR;
    __half* Vs = Ks + 128 * ASTR;

    int qt = blockIdx.x;              // 0/1
    int bh = blockIdx.y;
    int b = bh / H_, h = bh % H_;
    int tid = threadIdx.x, warp = tid >> 5, lane = tid & 31;
    int wm = warp * 16;
    int q0 = qt * 128;
    const __half* base = qkv + (size_t)b * T_ * QKVW + (size_t)h * D_;

    uint32_t qs_a = (uint32_t)__cvta_generic_to_shared(Qs);
    uint32_t ks_a = (uint32_t)__cvta_generic_to_shared(Ks);
    uint32_t vs_a = (uint32_t)__cvta_generic_to_shared(Vs);

    // load Q tile (128 x 64 halves)
    for (int i = tid; i < 128 * 8; i += 256) {
        int r = i >> 3, c = i & 7;
        *(float4*)(Qs + r * ASTR + c * 8) =
            *(const float4*)(base + (size_t)(q0 + r) * QKVW + c * 8);
    }

    float mlo = -1e30f, mhi = -1e30f, llo = 0.f, lhi = 0.f;
    float oacc[8][4];
    #pragma unroll
    for (int j = 0; j < 8; j++)
        #pragma unroll
        for (int e = 0; e < 4; e++) oacc[j][e] = 0.f;

    const float scale = 0.05103103630798287f;   // 1/sqrt(384)
    int qlo_g = q0 + wm + (lane >> 2);
    int qhi_g = qlo_g + 8;

    uint32_t qf[4][4];

    for (int kt = 0; kt <= qt; kt++) {
        int k0 = kt * 128;
        bool diag = (kt == qt);
        if (kt > 0) __syncthreads();
        for (int i = tid; i < 128 * 8; i += 256) {
            int r = i >> 3, c = i & 7;
            size_t roff = (size_t)(k0 + r) * QKVW + c * 8;
            *(float4*)(Ks + r * ASTR + c * 8) = *(const float4*)(base + C_  + roff);
            *(float4*)(Vs + r * ASTR + c * 8) = *(const float4*)(base + 2*C_ + roff);
        }
        __syncthreads();

        if (kt == 0) {
            #pragma unroll
            for (int kk = 0; kk < 4; kk++)
                ldsm_x4(qf[kk], qs_a + (uint32_t)(((wm + (lane & 15)) * ASTR
                                     + kk * 16 + ((lane >> 4) & 1) * 8) * 2));
        }

        #pragma unroll
        for (int c2 = 0; c2 < 2; c2++) {
            if (diag && c2 == 1 && wm < 64) continue;   // fully-masked chunk
            int kc0 = k0 + c2 * 64;

            // ---- S chunk = Q @ K^T : sacc[8][4] ----
            float sacc[8][4];
            #pragma unroll
            for (int j = 0; j < 8; j++)
                #pragma unroll
                for (int e = 0; e < 4; e++) sacc[j][e] = 0.f;

            #pragma unroll
            for (int kk = 0; kk < 4; kk++) {
                #pragma unroll
                for (int j2 = 0; j2 < 4; j2++) {
                    uint32_t kb[4];
                    ldsm_x4(kb, ks_a + (uint32_t)(((c2 * 64 + j2 * 16 + ((lane >> 4) & 1) * 8 + (lane & 7)) * ASTR
                                       + kk * 16 + ((lane >> 3) & 1) * 8) * 2));
                    mma_f16(sacc[2*j2],     qf[kk], kb);
                    mma_f16(sacc[2*j2 + 1], qf[kk], kb + 2);
                }
            }

            // ---- scale + causal mask + row max ----
            float rmlo = -1e30f, rmhi = -1e30f;
            #pragma unroll
            for (int j = 0; j < 8; j++) {
                int key = kc0 + 8 * j + 2 * (lane & 3);
                #pragma unroll
                for (int e = 0; e < 2; e++) {
                    float s = sacc[j][e] * scale;
                    if (diag && (key + e > qlo_g)) s = -1e30f;
                    sacc[j][e] = s;
                    rmlo = fmaxf(rmlo, s);
                }
                #pragma unroll
                for (int e = 2; e < 4; e++) {
                    float s = sacc[j][e] * scale;
                    if (diag && (key + e - 2 > qhi_g)) s = -1e30f;
                    sacc[j][e] = s;
                    rmhi = fmaxf(rmhi, s);
                }
            }
            rmlo = fmaxf(rmlo, __shfl_xor_sync(0xffffffffu, rmlo, 1));
            rmlo = fmaxf(rmlo, __shfl_xor_sync(0xffffffffu, rmlo, 2));
            rmhi = fmaxf(rmhi, __shfl_xor_sync(0xffffffffu, rmhi, 1));
            rmhi = fmaxf(rmhi, __shfl_xor_sync(0xffffffffu, rmhi, 2));

            float mnlo = fmaxf(mlo, rmlo), mnhi = fmaxf(mhi, rmhi);
            float elo = __expf(mlo - mnlo), ehi = __expf(mhi - mnhi);
            mlo = mnlo; mhi = mnhi;

            float slo = 0.f, shi = 0.f;
            #pragma unroll
            for (int j = 0; j < 8; j++) {
                float p0 = __expf(sacc[j][0] - mnlo);
                float p1 = __expf(sacc[j][1] - mnlo);
                float p2 = __expf(sacc[j][2] - mnhi);
                float p3 = __expf(sacc[j][3] - mnhi);
                sacc[j][0] = p0; sacc[j][1] = p1; sacc[j][2] = p2; sacc[j][3] = p3;
                slo += p0 + p1; shi += p2 + p3;
            }
            slo += __shfl_xor_sync(0xffffffffu, slo, 1);
            slo += __shfl_xor_sync(0xffffffffu, slo, 2);
            shi += __shfl_xor_sync(0xffffffffu, shi, 1);
            shi += __shfl_xor_sync(0xffffffffu, shi, 2);
            llo = llo * elo + slo;
            lhi = lhi * ehi + shi;

            #pragma unroll
            for (int j = 0; j < 8; j++) {
                oacc[j][0] *= elo; oacc[j][1] *= elo;
                oacc[j][2] *= ehi; oacc[j][3] *= ehi;
            }

            // ---- O += P @ V (64-key chunk = 4 k16 steps) ----
            #pragma unroll
            for (int kk2 = 0; kk2 < 4; kk2++) {
                uint32_t pa[4];
                pa[0] = pack_h2(sacc[2*kk2][0],   sacc[2*kk2][1]);
                pa[1] = pack_h2(sacc[2*kk2][2],   sacc[2*kk2][3]);
                pa[2] = pack_h2(sacc[2*kk2+1][0], sacc[2*kk2+1][1]);
                pa[3] = pack_h2(sacc[2*kk2+1][2], sacc[2*kk2+1][3]);
                #pragma unroll
                for (int j2 = 0; j2 < 4; j2++) {
                    uint32_t vb[4];
                    ldsm_x4t(vb, vs_a + (uint32_t)(((c2 * 64 + kk2 * 16 + ((lane >> 3) & 1) * 8 + (lane & 7)) * ASTR
                                        + j2 * 16 + ((lane >> 4) & 1) * 8) * 2));
                    mma_f16(oacc[2*j2],     pa, vb);
                    mma_f16(oacc[2*j2 + 1], pa, vb + 2);
                }
            }
        }
    }

    float ilo = 1.f / llo, ihi = 1.f / lhi;
    size_t rlo = (size_t)(b * T_ + qlo_g) * C_ + (size_t)h * D_;
    size_t rhi = (size_t)(b * T_ + qhi_g) * C_ + (size_t)h * D_;
    #pragma unroll
    for (int j = 0; j < 8; j++) {
        int col = 8 * j + 2 * (lane & 3);
        *(__half2*)(out + rlo + col) = __floats2half2_rn(oacc[j][0] * ilo, oacc[j][1] * ilo);
        *(__half2*)(out + rhi + col) = __floats2half2_rn(oacc[j][2] * ihi, oacc[j][3] * ihi);
    }
}

// ---------------- launch ----------------
extern "C" void kernel_launch(void* const* d_in, const int* in_sizes, int n_in,
                              void* d_out, int out_size)
{
    const float* x   = (const float*)d_in[0];
    const float* Wq  = (const float*)d_in[1];
    const float* Wk  = (const float*)d_in[2];
    const float* Wv  = (const float*)d_in[3];
    const float* Wp  = (const float*)d_in[4];
    const float* bp  = (const float*)d_in[5];
    const float* W1  = (const float*)d_in[6];
    const float* b1  = (const float*)d_in[7];
    const float* W2  = (const float*)d_in[8];
    const float* b2  = (const float*)d_in[9];
    const float* g1  = (const float*)d_in[10];
    const float* be1 = (const float*)d_in[11];
    const float* g2  = (const float*)d_in[12];
    const float* be2 = (const float*)d_in[13];
    float* out = (float*)d_out;

    __half *h1, *qkv, *attn, *h2, *mid, *WqkvT, *WpT, *W1T, *W2T;
    float *y1;
    cudaGetSymbolAddress((void**)&h1,    g_h1);
    cudaGetSymbolAddress((void**)&qkv,   g_qkv);
    cudaGetSymbolAddress((void**)&attn,  g_attn);
    cudaGetSymbolAddress((void**)&y1,    g_y1);
    cudaGetSymbolAddress((void**)&h2,    g_h2);
    cudaGetSymbolAddress((void**)&mid,   g_mid);
    cudaGetSymbolAddress((void**)&WqkvT, g_WqkvT);
    cudaGetSymbolAddress((void**)&WpT,   g_WpT);
    cudaGetSymbolAddress((void**)&W1T,   g_W1T);
    cudaGetSymbolAddress((void**)&W2T,   g_W2T);

    static const int FATTN_SMEM = 3 * 128 * ASTR * (int)sizeof(__half);   // 55296
    static const int GEMM_SMEM  = 3 * 2 * 128 * 80;                        // 61440
    cudaFuncSetAttribute(fattn_kernel, cudaFuncAttributeMaxDynamicSharedMemorySize, FATTN_SMEM);
    cudaFuncSetAttribute(mma_gemm<0, __half>, cudaFuncAttributeMaxDynamicSharedMemorySize, GEMM_SMEM);
    cudaFuncSetAttribute(mma_gemm<2, float>,  cudaFuncAttributeMaxDynamicSharedMemorySize, GEMM_SMEM);
    cudaFuncSetAttribute(mma_gemm<3, __half>, cudaFuncAttributeMaxDynamicSharedMemorySize, GEMM_SMEM);

    // 1. LN1 (fp16 out)
    ln_kernel<<<BT / 4, 128>>>(x, g1, be1, h1);

    // 2. weight repack/transpose to fp16 [N][K]
    repackT_kernel<<<(QKVW * C_ + 255) / 256, 256>>>(Wq, Wk, Wv, WqkvT);
    transpose_kernel<<<dim3(C_ / 32, C_ / 32), dim3(32, 8)>>>(Wp, WpT, C_, C_);
    transpose_kernel<<<dim3(C_ / 32, FF / 32), dim3(32, 8)>>>(W1, W1T, C_, FF);
    transpose_kernel<<<dim3(FF / 32, C_ / 32), dim3(32, 8)>>>(W2, W2T, FF, C_);

    // 3. qkv = h1 @ Wqkv           [32768 x 1152] fp16
    mma_gemm<0, __half><<<dim3(QKVW / 128, BT / 128), 256, GEMM_SMEM>>>(h1, WqkvT, nullptr, nullptr, qkv, BT, QKVW, C_);

    // 4. MMA flash attention       -> attn [32768 x 384] fp16
    fattn_kernel<<<dim3(2, B_ * H_), 256, FATTN_SMEM>>>(qkv, attn);

    // 5. y1 = x + attn @ Wp + bp   fp32
    mma_gemm<2, float><<<dim3(C_ / 128, BT / 128), 256, GEMM_SMEM>>>(attn, WpT, bp, x, y1, BT, C_, C_);

    // 6. LN2 (fp16 out)
    ln_kernel<<<BT / 4, 128>>>(y1, g2, be2, h2);

    // 7. mid = relu(h2 @ W1 + b1)  [32768 x 1536] fp16
    mma_gemm<3, __half><<<dim3(FF / 128, BT / 128), 256, GEMM_SMEM>>>(h2, W1T, b1, nullptr, mid, BT, FF, C_);

    // 8. out = y1 + mid @ W2 + b2  fp32
    mma_gemm<2, float><<<dim3(C_ / 128, BT / 128), 256, GEMM_SMEM>>>(mid, W2T, b2, y1, out, BT, C_, FF);
}